// round 8
// baseline (speedup 1.0000x reference)
#include <cuda_runtime.h>
#include <cuda_bf16.h>
#include <cstdint>

// ============================================================================
// TransformerEncoderLayer (B=4,S=4096,D=1024, 8 local heads) on sm_103 base.
// GEMMs: mma.sync.m16n8k16 bf16, 3-product double-bf16 split, fp32 accum.
// R7: 128x256 CTA tile / 512 threads / 2-stage cp.async; fused QKV (N=3072,
// packed [tok][3072] output); attn 2 tokens/block.
// ============================================================================

static const int M_TOK = 16384;
static const int DM    = 1024;

// ---------------- scratch (__device__ globals; allocation-free rule) --------
__device__ float g_qkv[16384 * 3072];              // packed q|k|v per token
__device__ float g_bqkv[3072];                     // concat bias
__device__ __nv_bfloat16 g_xhi [16384 * 1024];
__device__ __nv_bfloat16 g_xlo [16384 * 1024];
__device__ __nv_bfloat16 g_aohi[16384 * 1024];
__device__ __nv_bfloat16 g_aolo[16384 * 1024];
__device__ __nv_bfloat16 g_hhi [16384 * 1024];
__device__ __nv_bfloat16 g_hlo [16384 * 1024];
__device__ __nv_bfloat16 g_wthi[5][1024 * 1024];   // W^T hi [n][k] (q,k,v contiguous)
__device__ __nv_bfloat16 g_wtlo[5][1024 * 1024];   // W^T lo [n][k]

// ---------------- PTX helpers (sm_80-level; valid on sm_103 base) -----------
__device__ __forceinline__ uint32_t smem_u32(const void* p) {
    uint32_t a;
    asm("{ .reg .u64 t; cvta.to.shared.u64 t, %1; cvt.u32.u64 %0, t; }"
        : "=r"(a) : "l"(p));
    return a;
}
__device__ __forceinline__ void cpasync16(uint32_t saddr, const void* g) {
    asm volatile("cp.async.cg.shared.global [%0], [%1], 16;"
                 :: "r"(saddr), "l"(g));
}
#define CP_COMMIT() asm volatile("cp.async.commit_group;" ::: "memory")
#define CP_WAIT1()  asm volatile("cp.async.wait_group 1;" ::: "memory")

__device__ __forceinline__ void ldsm4(uint32_t r[4], uint32_t addr) {
    asm volatile("ldmatrix.sync.aligned.m8n8.x4.shared.b16 {%0,%1,%2,%3}, [%4];"
                 : "=r"(r[0]), "=r"(r[1]), "=r"(r[2]), "=r"(r[3]) : "r"(addr));
}
__device__ __forceinline__ void mma16816(float c[4], const uint32_t a[4],
                                         uint32_t b0, uint32_t b1) {
    asm volatile(
        "mma.sync.aligned.m16n8k16.row.col.f32.bf16.bf16.f32 "
        "{%0,%1,%2,%3}, {%4,%5,%6,%7}, {%8,%9}, {%0,%1,%2,%3};"
        : "+f"(c[0]), "+f"(c[1]), "+f"(c[2]), "+f"(c[3])
        : "r"(a[0]), "r"(a[1]), "r"(a[2]), "r"(a[3]), "r"(b0), "r"(b1));
}
__device__ __forceinline__ uint32_t pack_hi_lo(float x, float y, uint32_t& lo_out) {
    const __nv_bfloat16 hx = __float2bfloat16(x);
    const __nv_bfloat16 hy = __float2bfloat16(y);
    const __nv_bfloat16 lx = __float2bfloat16(x - __bfloat162float(hx));
    const __nv_bfloat16 ly = __float2bfloat16(y - __bfloat162float(hy));
    union { __nv_bfloat16 b[2]; uint32_t u; } h, l;
    h.b[0] = hx; h.b[1] = hy; l.b[0] = lx; l.b[1] = ly;
    lo_out = l.u;
    return h.u;
}

// smem: 2 stages x 96KB; stage = Ahi@0(16K), Alo@16K, Bhi@32K(32K), Blo@64K(32K)
// A: 128 rows x 128B (BK=64 bf16); B: 256 rows x 128B. SW128 swizzle.
static const int STAGE_BYTES = 98304;
static const int SMEM_DYN    = 2 * STAGE_BYTES;    // 192KB

// ============================================================================
// GEMM D[M x N] = A @ W + bias. A split (hi,lo) [m][1024], W^T split [n][1024].
// CTA tile 128x256, 512 thr (16 warps: 2m x 8n, warp tile 64x32), BK=64.
// Out: fp32 Cf and/or bf16 split (Chi,Clo), leading dim Nld, optional ReLU.
// ============================================================================
__global__ __launch_bounds__(512, 1)
void gemm_mma_bf16x3(const __nv_bfloat16* __restrict__ Ahi, const __nv_bfloat16* __restrict__ Alo,
                     const __nv_bfloat16* __restrict__ Bhi, const __nv_bfloat16* __restrict__ Blo,
                     const float* __restrict__ bias,
                     float* __restrict__ Cf,
                     __nv_bfloat16* __restrict__ Chi, __nv_bfloat16* __restrict__ Clo,
                     int relu, int Nld)
{
    extern __shared__ char smem[];
    const uint32_t sbase = smem_u32(smem);
    const int tid  = threadIdx.x;
    const int lane = tid & 31;
    const int wid  = tid >> 5;
    const int wm   = wid >> 3;          // 0..1 (m: 64 each)
    const int wn   = wid & 7;           // 0..7 (n: 32 each)
    const int m0   = blockIdx.y * 128;
    const int n0   = blockIdx.x * 256;

    float acc[4][4][4];
    #pragma unroll
    for (int a = 0; a < 4; ++a)
        #pragma unroll
        for (int n = 0; n < 4; ++n)
            #pragma unroll
            for (int e = 0; e < 4; ++e) acc[a][n][e] = 0.0f;

    // ---- gmem->smem: 8 threads per 128B row; A 2 rows/thr, B 4 rows/thr ----
    const int lrow = tid >> 3;                  // 0..63
    const int lc   = tid & 7;                   // 16B granule
    auto issue_tile = [&](int t) {
        const uint32_t st = sbase + (uint32_t)(t & 1) * (uint32_t)STAGE_BYTES;
        const int kt = t * 64;
        #pragma unroll
        for (int j = 0; j < 2; ++j) {
            const int row = j * 64 + lrow;
            const uint32_t so = (uint32_t)row * 128u +
                                (((uint32_t)lc * 16u) ^ (((uint32_t)row & 7u) << 4));
            const size_t ga = (size_t)(m0 + row) * 1024 + kt + lc * 8;
            cpasync16(st +          so, Ahi + ga);
            cpasync16(st + 16384u + so, Alo + ga);
        }
        #pragma unroll
        for (int j = 0; j < 4; ++j) {
            const int row = j * 64 + lrow;      // 0..255
            const uint32_t so = (uint32_t)row * 128u +
                                (((uint32_t)lc * 16u) ^ (((uint32_t)row & 7u) << 4));
            const size_t gb = (size_t)(n0 + row) * 1024 + kt + lc * 8;
            cpasync16(st + 32768u + so, Bhi + gb);
            cpasync16(st + 65536u + so, Blo + gb);
        }
    };

    // ---- ldmatrix per-thread constants ------------------------------------
    const int mi = lane >> 3, li = lane & 7;
    const uint32_t axor  = ((uint32_t)li) << 4;
    const int      arow0 = wm * 64 + ((mi & 1) << 3) + li;
    const uint32_t acb0  = ((uint32_t)(mi >> 1)) << 4;
    const int      brow0 = wn * 32 + ((mi >> 1) << 3) + li;
    const uint32_t bcb0  = ((uint32_t)(mi & 1)) << 4;

    issue_tile(0); CP_COMMIT();
    issue_tile(1); CP_COMMIT();

    for (int t = 0; t < 16; ++t) {
        CP_WAIT1();
        __syncthreads();

        const uint32_t st = sbase + (uint32_t)(t & 1) * (uint32_t)STAGE_BYTES;
        #pragma unroll
        for (int ks = 0; ks < 4; ++ks) {
            const uint32_t kc = (uint32_t)ks * 32u;
            uint32_t aH[4][4], aL[4][4], bH[2][4], bL[2][4];

            #pragma unroll
            for (int a = 0; a < 4; ++a)
                ldsm4(aH[a], st + (uint32_t)(arow0 + a * 16) * 128u + ((kc + acb0) ^ axor));
            #pragma unroll
            for (int g = 0; g < 2; ++g)
                ldsm4(bH[g], st + 32768u + (uint32_t)(brow0 + g * 16) * 128u + ((kc + bcb0) ^ axor));
            #pragma unroll
            for (int a = 0; a < 4; ++a)
                #pragma unroll
                for (int n = 0; n < 4; ++n)
                    mma16816(acc[a][n], aH[a], bH[n >> 1][(n & 1) * 2], bH[n >> 1][(n & 1) * 2 + 1]);

            #pragma unroll
            for (int g = 0; g < 2; ++g)
                ldsm4(bL[g], st + 65536u + (uint32_t)(brow0 + g * 16) * 128u + ((kc + bcb0) ^ axor));
            #pragma unroll
            for (int a = 0; a < 4; ++a)
                #pragma unroll
                for (int n = 0; n < 4; ++n)
                    mma16816(acc[a][n], aH[a], bL[n >> 1][(n & 1) * 2], bL[n >> 1][(n & 1) * 2 + 1]);

            #pragma unroll
            for (int a = 0; a < 4; ++a)
                ldsm4(aL[a], st + 16384u + (uint32_t)(arow0 + a * 16) * 128u + ((kc + acb0) ^ axor));
            #pragma unroll
            for (int a = 0; a < 4; ++a)
                #pragma unroll
                for (int n = 0; n < 4; ++n)
                    mma16816(acc[a][n], aL[a], bH[n >> 1][(n & 1) * 2], bH[n >> 1][(n & 1) * 2 + 1]);
        }
        __syncthreads();

        if (t + 2 < 16) issue_tile(t + 2);
        CP_COMMIT();
    }

    // ---- epilogue ----------------------------------------------------------
    const int er0 = m0 + wm * 64 + (lane >> 2);
    const int ec0 = n0 + wn * 32 + (lane & 3) * 2;
    #pragma unroll
    for (int a = 0; a < 4; ++a) {
        #pragma unroll
        for (int n = 0; n < 4; ++n) {
            const int r0 = er0 + a * 16, r1 = r0 + 8;
            const int c  = ec0 + n * 8;
            const float b0 = __ldg(bias + c), b1 = __ldg(bias + c + 1);
            float v00 = acc[a][n][0] + b0, v01 = acc[a][n][1] + b1;
            float v10 = acc[a][n][2] + b0, v11 = acc[a][n][3] + b1;
            if (relu) {
                v00 = fmaxf(v00, 0.0f); v01 = fmaxf(v01, 0.0f);
                v10 = fmaxf(v10, 0.0f); v11 = fmaxf(v11, 0.0f);
            }
            if (Cf) {
                *(float2*)(Cf + (size_t)r0 * Nld + c) = make_float2(v00, v01);
                *(float2*)(Cf + (size_t)r1 * Nld + c) = make_float2(v10, v11);
            }
            if (Chi) {
                uint32_t l0, l1;
                const uint32_t h0 = pack_hi_lo(v00, v01, l0);
                const uint32_t h1 = pack_hi_lo(v10, v11, l1);
                *(uint32_t*)(Chi + (size_t)r0 * Nld + c) = h0;
                *(uint32_t*)(Clo + (size_t)r0 * Nld + c) = l0;
                *(uint32_t*)(Chi + (size_t)r1 * Nld + c) = h1;
                *(uint32_t*)(Clo + (size_t)r1 * Nld + c) = l1;
            }
        }
    }
}

// ============================================================================
// fp32 -> bf16 hi/lo elementwise split (for x)
// ============================================================================
__global__ void split_kernel(const float* __restrict__ X,
                             __nv_bfloat16* __restrict__ H,
                             __nv_bfloat16* __restrict__ L, int n4)
{
    const int i = blockIdx.x * blockDim.x + threadIdx.x;
    if (i >= n4) return;
    const float4 v = ((const float4*)X)[i];
    const float vv[4] = {v.x, v.y, v.z, v.w};
    union { __nv_bfloat16 b[4]; uint2 u; } hh, ll;
    #pragma unroll
    for (int e = 0; e < 4; ++e) {
        const __nv_bfloat16 hb = __float2bfloat16(vv[e]);
        hh.b[e] = hb;
        ll.b[e] = __float2bfloat16(vv[e] - __bfloat162float(hb));
    }
    ((uint2*)H)[i] = hh.u;
    ((uint2*)L)[i] = ll.u;
}

// ============================================================================
// W [k][n] fp32 -> W^T hi/lo [n][k] bf16 (tiled transpose + split)
// ============================================================================
__global__ void wconvert_kernel(const float* __restrict__ W,
                                __nv_bfloat16* __restrict__ Thi,
                                __nv_bfloat16* __restrict__ Tlo)
{
    __shared__ float t[32][33];
    const int k0 = blockIdx.y * 32, n0 = blockIdx.x * 32;
    const int tx = threadIdx.x, ty = threadIdx.y;  // 32 x 8
    #pragma unroll
    for (int i = 0; i < 4; ++i)
        t[ty + i*8][tx] = W[(size_t)(k0 + ty + i*8) * 1024 + n0 + tx];
    __syncthreads();
    #pragma unroll
    for (int i = 0; i < 4; ++i) {
        const float v = t[tx][ty + i*8];
        const size_t o = (size_t)(n0 + ty + i*8) * 1024 + k0 + tx;
        const __nv_bfloat16 hb = __float2bfloat16(v);
        Thi[o] = hb;
        Tlo[o] = __float2bfloat16(v - __bfloat162float(hb));
    }
}

// ============================================================================
// Per-token 8-head local attention; packed qkv [tok][3072] input;
// 2 tokens per 256-thread block; emits bf16 hi/lo output + attn weights.
// ============================================================================
__global__ __launch_bounds__(256)
void attn_kernel(const float* __restrict__ QKV,
                 __nv_bfloat16* __restrict__ Ohi, __nv_bfloat16* __restrict__ Olo,
                 float* __restrict__ AW)
{
    __shared__ float sq[2][8 * 132];
    __shared__ float sk[2][8 * 132];
    __shared__ float sv[2][8 * 132];
    __shared__ float sw[2][64];

    const int sub = threadIdx.x >> 7;            // token within block
    const int tid = threadIdx.x & 127;
    const size_t tok  = (size_t)blockIdx.x * 2 + sub;
    const size_t base = tok * 3072;

    float* q_ = sq[sub]; float* k_ = sk[sub]; float* v_ = sv[sub]; float* w_ = sw[sub];

    for (int i = tid; i < 1024; i += 128) {
        const int h = i >> 7, d = i & 127;
        q_[h * 132 + d] = QKV[base + i];
        k_[h * 132 + d] = QKV[base + 1024 + i];
        v_[h * 132 + d] = QKV[base + 2048 + i];
    }
    __syncthreads();

    if (tid < 64) {
        const int h = tid >> 3, t = tid & 7;
        float s = 0.0f;
        #pragma unroll 8
        for (int d = 0; d < 128; d++)
            s += q_[h * 132 + d] * k_[t * 132 + d];
        w_[tid] = s * 0.08838834764831845f;      // 1/sqrt(128)
    }
    __syncthreads();

    if (tid < 8) {
        const int h = tid;
        float m = w_[h * 8];
        #pragma unroll
        for (int t = 1; t < 8; t++) m = fmaxf(m, w_[h * 8 + t]);
        float e[8], sum = 0.0f;
        #pragma unroll
        for (int t = 0; t < 8; t++) { e[t] = expf(w_[h * 8 + t] - m); sum += e[t]; }
        const float inv = 1.0f / sum;
        #pragma unroll
        for (int t = 0; t < 8; t++) w_[h * 8 + t] = e[t] * inv;
    }
    __syncthreads();

    const int d = tid;
    const size_t obase = tok * 1024;
    #pragma unroll
    for (int h = 0; h < 8; h++) {
        float o = 0.0f;
        #pragma unroll
        for (int t = 0; t < 8; t++)
            o += w_[h * 8 + t] * v_[t * 132 + d];
        const __nv_bfloat16 hb = __float2bfloat16(o);
        Ohi[obase + h * 128 + d] = hb;
        Olo[obase + h * 128 + d] = __float2bfloat16(o - __bfloat162float(hb));
    }

    if (AW != nullptr && tid < 64)
        AW[tok * 64 + tid] = w_[tid];
}

// ============================================================================
extern "C" void kernel_launch(void* const* d_in, const int* in_sizes, int n_in,
                              void* d_out, int out_size)
{
    (void)in_sizes; (void)n_in;
    const float* x  = (const float*)d_in[0];
    const float* W[5]  = { (const float*)d_in[1], (const float*)d_in[3],
                           (const float*)d_in[5], (const float*)d_in[7],
                           (const float*)d_in[9] };   // Wq, Wk, Wv, W1, W2
    const float* bq = (const float*)d_in[2];
    const float* bk = (const float*)d_in[4];
    const float* bv = (const float*)d_in[6];
    const float* b1 = (const float*)d_in[8];
    const float* b2 = (const float*)d_in[10];
    float* out = (float*)d_out;

    float *qkv, *bqkv;
    __nv_bfloat16 *xhi, *xlo, *aohi, *aolo, *hhi, *hlo, *wthi, *wtlo;
    cudaGetSymbolAddress((void**)&qkv,  g_qkv);
    cudaGetSymbolAddress((void**)&bqkv, g_bqkv);
    cudaGetSymbolAddress((void**)&xhi,  g_xhi);
    cudaGetSymbolAddress((void**)&xlo,  g_xlo);
    cudaGetSymbolAddress((void**)&aohi, g_aohi);
    cudaGetSymbolAddress((void**)&aolo, g_aolo);
    cudaGetSymbolAddress((void**)&hhi,  g_hhi);
    cudaGetSymbolAddress((void**)&hlo,  g_hlo);
    cudaGetSymbolAddress((void**)&wthi, g_wthi);
    cudaGetSymbolAddress((void**)&wtlo, g_wtlo);

    cudaFuncSetAttribute(gemm_mma_bf16x3,
                         cudaFuncAttributeMaxDynamicSharedMemorySize, SMEM_DYN);

    const int ff_elems   = M_TOK * DM;
    const int attn_elems = M_TOK * 64;
    float* aw = (out_size >= ff_elems + attn_elems) ? (out + ff_elems) : nullptr;

    // ---- prep: split x; transpose+split weights; concat qkv bias ----------
    split_kernel<<<(M_TOK * DM / 4 + 255) / 256, 256>>>(x, xhi, xlo, M_TOK * DM / 4);
    for (int i = 0; i < 5; ++i)
        wconvert_kernel<<<dim3(32, 32), dim3(32, 8)>>>(W[i],
            wthi + (size_t)i * DM * DM, wtlo + (size_t)i * DM * DM);
    cudaMemcpyAsync(bqkv,        bq, 1024 * sizeof(float), cudaMemcpyDeviceToDevice);
    cudaMemcpyAsync(bqkv + 1024, bk, 1024 * sizeof(float), cudaMemcpyDeviceToDevice);
    cudaMemcpyAsync(bqkv + 2048, bv, 1024 * sizeof(float), cudaMemcpyDeviceToDevice);

    dim3 block(512);

    // ---- fused QKV projection: N=3072, packed [tok][3072] fp32 ------------
    gemm_mma_bf16x3<<<dim3(12, 128), block, SMEM_DYN>>>(xhi, xlo,
        wthi, wtlo, bqkv, qkv, nullptr, nullptr, 0, 3072);

    // ---- attention (emits bf16 split for FFN1) ----------------------------
    attn_kernel<<<M_TOK / 2, 256>>>(qkv, aohi, aolo, aw);

    // ---- FFN --------------------------------------------------------------
    gemm_mma_bf16x3<<<dim3(4, 128), block, SMEM_DYN>>>(aohi, aolo,
        wthi + 3 * (size_t)DM * DM, wtlo + 3 * (size_t)DM * DM, b1,
        nullptr, hhi, hlo, 1, 1024);
    gemm_mma_bf16x3<<<dim3(4, 128), block, SMEM_DYN>>>(hhi, hlo,
        wthi + 4 * (size_t)DM * DM, wtlo + 4 * (size_t)DM * DM, b2,
        out, nullptr, nullptr, 0, 1024);
}

// round 9
// speedup vs baseline: 1.0588x; 1.0588x over previous
#include <cuda_runtime.h>
#include <cuda_bf16.h>
#include <cstdint>

// ============================================================================
// TransformerEncoderLayer (B=4,S=4096,D=1024, 8 local heads) on sm_103 base.
// GEMMs: mma.sync.m16n8k16 bf16, 3-product double-bf16 split, fp32 accum.
// R8: proven R6 GEMM core (256 thr, 128x128, BK=64, 3-stage cp.async,
// issue-before-compute) + fused QKV (N=3072) + all-fragments-preload +
// merged weight-convert prep.
// ============================================================================

static const int M_TOK = 16384;
static const int DM    = 1024;

// ---------------- scratch (__device__ globals; allocation-free rule) --------
__device__ float g_qkv[16384 * 3072];              // packed q|k|v per token
__device__ float g_bqkv[3072];                     // concat bias
__device__ __nv_bfloat16 g_xhi [16384 * 1024];
__device__ __nv_bfloat16 g_xlo [16384 * 1024];
__device__ __nv_bfloat16 g_aohi[16384 * 1024];
__device__ __nv_bfloat16 g_aolo[16384 * 1024];
__device__ __nv_bfloat16 g_hhi [16384 * 1024];
__device__ __nv_bfloat16 g_hlo [16384 * 1024];
__device__ __nv_bfloat16 g_wthi[5][1024 * 1024];   // W^T hi [n][k] (q,k,v contiguous)
__device__ __nv_bfloat16 g_wtlo[5][1024 * 1024];   // W^T lo [n][k]

// ---------------- PTX helpers (sm_80-level; valid on sm_103 base) -----------
__device__ __forceinline__ uint32_t smem_u32(const void* p) {
    uint32_t a;
    asm("{ .reg .u64 t; cvta.to.shared.u64 t, %1; cvt.u32.u64 %0, t; }"
        : "=r"(a) : "l"(p));
    return a;
}
__device__ __forceinline__ void cpasync16(uint32_t saddr, const void* g) {
    asm volatile("cp.async.cg.shared.global [%0], [%1], 16;"
                 :: "r"(saddr), "l"(g));
}
#define CP_COMMIT() asm volatile("cp.async.commit_group;" ::: "memory")
#define CP_WAIT1()  asm volatile("cp.async.wait_group 1;" ::: "memory")

__device__ __forceinline__ void ldsm4(uint32_t r[4], uint32_t addr) {
    asm volatile("ldmatrix.sync.aligned.m8n8.x4.shared.b16 {%0,%1,%2,%3}, [%4];"
                 : "=r"(r[0]), "=r"(r[1]), "=r"(r[2]), "=r"(r[3]) : "r"(addr));
}
__device__ __forceinline__ void mma16816(float c[4], const uint32_t a[4],
                                         uint32_t b0, uint32_t b1) {
    asm volatile(
        "mma.sync.aligned.m16n8k16.row.col.f32.bf16.bf16.f32 "
        "{%0,%1,%2,%3}, {%4,%5,%6,%7}, {%8,%9}, {%0,%1,%2,%3};"
        : "+f"(c[0]), "+f"(c[1]), "+f"(c[2]), "+f"(c[3])
        : "r"(a[0]), "r"(a[1]), "r"(a[2]), "r"(a[3]), "r"(b0), "r"(b1));
}
__device__ __forceinline__ uint32_t pack_hi_lo(float x, float y, uint32_t& lo_out) {
    const __nv_bfloat16 hx = __float2bfloat16(x);
    const __nv_bfloat16 hy = __float2bfloat16(y);
    const __nv_bfloat16 lx = __float2bfloat16(x - __bfloat162float(hx));
    const __nv_bfloat16 ly = __float2bfloat16(y - __bfloat162float(hy));
    union { __nv_bfloat16 b[2]; uint32_t u; } h, l;
    h.b[0] = hx; h.b[1] = hy; l.b[0] = lx; l.b[1] = ly;
    lo_out = l.u;
    return h.u;
}

// smem: 3 stages x 64KB; stage = Ahi@0, Alo@16K, Bhi@32K, Blo@48K,
// each operand 128 rows x 128B (BK=64 bf16), SW128 swizzle.
static const int SMEM_DYN = 3 * 65536;

// ============================================================================
// GEMM D[M x N] = A @ W + bias. A split (hi,lo) [m][1024], W^T split [n][1024].
// CTA 128x128, 256 thr (8 warps: 2m x 4n, warp tile 64x32), BK=64, 3 stages.
// Out: fp32 Cf and/or bf16 split (Chi,Clo) with leading dim Nld; optional ReLU.
// ============================================================================
__global__ __launch_bounds__(256, 1)
void gemm_mma_bf16x3(const __nv_bfloat16* __restrict__ Ahi, const __nv_bfloat16* __restrict__ Alo,
                     const __nv_bfloat16* __restrict__ Bhi, const __nv_bfloat16* __restrict__ Blo,
                     const float* __restrict__ bias,
                     float* __restrict__ Cf,
                     __nv_bfloat16* __restrict__ Chi, __nv_bfloat16* __restrict__ Clo,
                     int relu, int Nld)
{
    extern __shared__ char smem[];
    const uint32_t sbase = smem_u32(smem);
    const int tid  = threadIdx.x;
    const int lane = tid & 31;
    const int wid  = tid >> 5;
    const int wm   = wid >> 2;          // 0..1  (m: 64 each)
    const int wn   = wid & 3;           // 0..3  (n: 32 each)
    const int m0   = blockIdx.y * 128;
    const int n0   = blockIdx.x * 128;

    float acc[4][4][4];
    #pragma unroll
    for (int a = 0; a < 4; ++a)
        #pragma unroll
        for (int n = 0; n < 4; ++n)
            #pragma unroll
            for (int e = 0; e < 4; ++e) acc[a][n][e] = 0.0f;

    // ---- gmem->smem mapping: 8 threads per 128B row, all 8 granules -------
    const int lrow = tid >> 3;                  // 0..31, + j*32
    const int lc   = tid & 7;                   // 16B granule
    auto issue_tile = [&](int t) {
        const uint32_t st = sbase + (uint32_t)(t % 3) * 65536u;
        const int kt = t * 64;
        #pragma unroll
        for (int j = 0; j < 4; ++j) {
            const int row = j * 32 + lrow;
            const uint32_t so = (uint32_t)row * 128u +
                                (((uint32_t)lc * 16u) ^ (((uint32_t)row & 7u) << 4));
            const size_t ga = (size_t)(m0 + row) * 1024 + kt + lc * 8;
            const size_t gb = (size_t)(n0 + row) * 1024 + kt + lc * 8;
            cpasync16(st +          so, Ahi + ga);
            cpasync16(st + 16384u + so, Alo + ga);
            cpasync16(st + 32768u + so, Bhi + gb);
            cpasync16(st + 49152u + so, Blo + gb);
        }
    };

    // ---- ldmatrix per-thread constants -------------------------------------
    const int mi = lane >> 3, li = lane & 7;
    const uint32_t axor  = ((uint32_t)li) << 4;                 // swizzle xor
    const int      arow0 = wm * 64 + ((mi & 1) << 3) + li;      // + a*16
    const uint32_t acb0  = ((uint32_t)(mi >> 1)) << 4;          // + ks*32
    const int      brow0 = wn * 32 + ((mi >> 1) << 3) + li;     // + g*16
    const uint32_t bcb0  = ((uint32_t)(mi & 1)) << 4;           // + ks*32

    // ---- pipeline: 3-stage cp.async, issue-before-compute ------------------
    issue_tile(0); CP_COMMIT();
    issue_tile(1); CP_COMMIT();

    for (int t = 0; t < 16; ++t) {
        CP_WAIT1();
        __syncthreads();
        if (t + 2 < 16) issue_tile(t + 2);
        CP_COMMIT();

        const uint32_t st = sbase + (uint32_t)(t % 3) * 65536u;
        #pragma unroll
        for (int ks = 0; ks < 4; ++ks) {
            const uint32_t kc = (uint32_t)ks * 32u;
            uint32_t aH[4][4], aL[4][4], bH[2][4], bL[2][4];

            // Preload ALL fragments for this ks-step, then do all 48 MMAs.
            #pragma unroll
            for (int a = 0; a < 4; ++a)
                ldsm4(aH[a], st + (uint32_t)(arow0 + a * 16) * 128u + ((kc + acb0) ^ axor));
            #pragma unroll
            for (int g = 0; g < 2; ++g)
                ldsm4(bH[g], st + 32768u + (uint32_t)(brow0 + g * 16) * 128u + ((kc + bcb0) ^ axor));
            #pragma unroll
            for (int g = 0; g < 2; ++g)
                ldsm4(bL[g], st + 49152u + (uint32_t)(brow0 + g * 16) * 128u + ((kc + bcb0) ^ axor));
            #pragma unroll
            for (int a = 0; a < 4; ++a)
                ldsm4(aL[a], st + 16384u + (uint32_t)(arow0 + a * 16) * 128u + ((kc + acb0) ^ axor));

            #pragma unroll
            for (int a = 0; a < 4; ++a)
                #pragma unroll
                for (int n = 0; n < 4; ++n)
                    mma16816(acc[a][n], aH[a], bH[n >> 1][(n & 1) * 2], bH[n >> 1][(n & 1) * 2 + 1]);
            #pragma unroll
            for (int a = 0; a < 4; ++a)
                #pragma unroll
                for (int n = 0; n < 4; ++n)
                    mma16816(acc[a][n], aH[a], bL[n >> 1][(n & 1) * 2], bL[n >> 1][(n & 1) * 2 + 1]);
            #pragma unroll
            for (int a = 0; a < 4; ++a)
                #pragma unroll
                for (int n = 0; n < 4; ++n)
                    mma16816(acc[a][n], aL[a], bH[n >> 1][(n & 1) * 2], bH[n >> 1][(n & 1) * 2 + 1]);
        }
    }

    // ---- epilogue ----------------------------------------------------------
    const int er0 = m0 + wm * 64 + (lane >> 2);
    const int ec0 = n0 + wn * 32 + (lane & 3) * 2;
    #pragma unroll
    for (int a = 0; a < 4; ++a) {
        #pragma unroll
        for (int n = 0; n < 4; ++n) {
            const int r0 = er0 + a * 16, r1 = r0 + 8;
            const int c  = ec0 + n * 8;
            const float b0 = __ldg(bias + c), b1 = __ldg(bias + c + 1);
            float v00 = acc[a][n][0] + b0, v01 = acc[a][n][1] + b1;
            float v10 = acc[a][n][2] + b0, v11 = acc[a][n][3] + b1;
            if (relu) {
                v00 = fmaxf(v00, 0.0f); v01 = fmaxf(v01, 0.0f);
                v10 = fmaxf(v10, 0.0f); v11 = fmaxf(v11, 0.0f);
            }
            if (Cf) {
                *(float2*)(Cf + (size_t)r0 * Nld + c) = make_float2(v00, v01);
                *(float2*)(Cf + (size_t)r1 * Nld + c) = make_float2(v10, v11);
            }
            if (Chi) {
                uint32_t l0, l1;
                const uint32_t h0 = pack_hi_lo(v00, v01, l0);
                const uint32_t h1 = pack_hi_lo(v10, v11, l1);
                *(uint32_t*)(Chi + (size_t)r0 * Nld + c) = h0;
                *(uint32_t*)(Clo + (size_t)r0 * Nld + c) = l0;
                *(uint32_t*)(Chi + (size_t)r1 * Nld + c) = h1;
                *(uint32_t*)(Clo + (size_t)r1 * Nld + c) = l1;
            }
        }
    }
}

// ============================================================================
// fp32 -> bf16 hi/lo elementwise split (for x)
// ============================================================================
__global__ void split_kernel(const float* __restrict__ X,
                             __nv_bfloat16* __restrict__ H,
                             __nv_bfloat16* __restrict__ L, int n4)
{
    const int i = blockIdx.x * blockDim.x + threadIdx.x;
    if (i >= n4) return;
    const float4 v = ((const float4*)X)[i];
    const float vv[4] = {v.x, v.y, v.z, v.w};
    union { __nv_bfloat16 b[4]; uint2 u; } hh, ll;
    #pragma unroll
    for (int e = 0; e < 4; ++e) {
        const __nv_bfloat16 hb = __float2bfloat16(vv[e]);
        hh.b[e] = hb;
        ll.b[e] = __float2bfloat16(vv[e] - __bfloat162float(hb));
    }
    ((uint2*)H)[i] = hh.u;
    ((uint2*)L)[i] = ll.u;
}

// ============================================================================
// All 5 weights: W [k][n] fp32 -> W^T hi/lo [n][k] bf16. gridDim.z selects W.
// ============================================================================
__global__ void wconvert_kernel(const float* __restrict__ W0, const float* __restrict__ W1,
                                const float* __restrict__ W2, const float* __restrict__ W3,
                                const float* __restrict__ W4,
                                __nv_bfloat16* __restrict__ Thi,
                                __nv_bfloat16* __restrict__ Tlo)
{
    __shared__ float t[32][33];
    const int wi = blockIdx.z;
    const float* W = (wi == 0) ? W0 : (wi == 1) ? W1 : (wi == 2) ? W2
                   : (wi == 3) ? W3 : W4;
    __nv_bfloat16* H = Thi + (size_t)wi * 1024 * 1024;
    __nv_bfloat16* L = Tlo + (size_t)wi * 1024 * 1024;

    const int k0 = blockIdx.y * 32, n0 = blockIdx.x * 32;
    const int tx = threadIdx.x, ty = threadIdx.y;  // 32 x 8
    #pragma unroll
    for (int i = 0; i < 4; ++i)
        t[ty + i*8][tx] = W[(size_t)(k0 + ty + i*8) * 1024 + n0 + tx];
    __syncthreads();
    #pragma unroll
    for (int i = 0; i < 4; ++i) {
        const float v = t[tx][ty + i*8];
        const size_t o = (size_t)(n0 + ty + i*8) * 1024 + k0 + tx;
        const __nv_bfloat16 hb = __float2bfloat16(v);
        H[o] = hb;
        L[o] = __float2bfloat16(v - __bfloat162float(hb));
    }
}

// ============================================================================
// Per-token 8-head local attention; packed qkv [tok][3072] input;
// 2 tokens per 256-thread block; emits bf16 hi/lo output + attn weights.
// ============================================================================
__global__ __launch_bounds__(256)
void attn_kernel(const float* __restrict__ QKV,
                 __nv_bfloat16* __restrict__ Ohi, __nv_bfloat16* __restrict__ Olo,
                 float* __restrict__ AW)
{
    __shared__ float sq[2][8 * 132];
    __shared__ float sk[2][8 * 132];
    __shared__ float sv[2][8 * 132];
    __shared__ float sw[2][64];

    const int sub = threadIdx.x >> 7;            // token within block
    const int tid = threadIdx.x & 127;
    const size_t tok  = (size_t)blockIdx.x * 2 + sub;
    const size_t base = tok * 3072;

    float* q_ = sq[sub]; float* k_ = sk[sub]; float* v_ = sv[sub]; float* w_ = sw[sub];

    for (int i = tid; i < 1024; i += 128) {
        const int h = i >> 7, d = i & 127;
        q_[h * 132 + d] = QKV[base + i];
        k_[h * 132 + d] = QKV[base + 1024 + i];
        v_[h * 132 + d] = QKV[base + 2048 + i];
    }
    __syncthreads();

    if (tid < 64) {
        const int h = tid >> 3, t = tid & 7;
        float s = 0.0f;
        #pragma unroll 8
        for (int d = 0; d < 128; d++)
            s += q_[h * 132 + d] * k_[t * 132 + d];
        w_[tid] = s * 0.08838834764831845f;      // 1/sqrt(128)
    }
    __syncthreads();

    if (tid < 8) {
        const int h = tid;
        float m = w_[h * 8];
        #pragma unroll
        for (int t = 1; t < 8; t++) m = fmaxf(m, w_[h * 8 + t]);
        float e[8], sum = 0.0f;
        #pragma unroll
        for (int t = 0; t < 8; t++) { e[t] = expf(w_[h * 8 + t] - m); sum += e[t]; }
        const float inv = 1.0f / sum;
        #pragma unroll
        for (int t = 0; t < 8; t++) w_[h * 8 + t] = e[t] * inv;
    }
    __syncthreads();

    const int d = tid;
    const size_t obase = tok * 1024;
    #pragma unroll
    for (int h = 0; h < 8; h++) {
        float o = 0.0f;
        #pragma unroll
        for (int t = 0; t < 8; t++)
            o += w_[h * 8 + t] * v_[t * 132 + d];
        const __nv_bfloat16 hb = __float2bfloat16(o);
        Ohi[obase + h * 128 + d] = hb;
        Olo[obase + h * 128 + d] = __float2bfloat16(o - __bfloat162float(hb));
    }

    if (AW != nullptr && tid < 64)
        AW[tok * 64 + tid] = w_[tid];
}

// ============================================================================
extern "C" void kernel_launch(void* const* d_in, const int* in_sizes, int n_in,
                              void* d_out, int out_size)
{
    (void)in_sizes; (void)n_in;
    const float* x  = (const float*)d_in[0];
    const float* bq = (const float*)d_in[2];
    const float* bk = (const float*)d_in[4];
    const float* bv = (const float*)d_in[6];
    const float* b1 = (const float*)d_in[8];
    const float* b2 = (const float*)d_in[10];
    float* out = (float*)d_out;

    float *qkv, *bqkv;
    __nv_bfloat16 *xhi, *xlo, *aohi, *aolo, *hhi, *hlo, *wthi, *wtlo;
    cudaGetSymbolAddress((void**)&qkv,  g_qkv);
    cudaGetSymbolAddress((void**)&bqkv, g_bqkv);
    cudaGetSymbolAddress((void**)&xhi,  g_xhi);
    cudaGetSymbolAddress((void**)&xlo,  g_xlo);
    cudaGetSymbolAddress((void**)&aohi, g_aohi);
    cudaGetSymbolAddress((void**)&aolo, g_aolo);
    cudaGetSymbolAddress((void**)&hhi,  g_hhi);
    cudaGetSymbolAddress((void**)&hlo,  g_hlo);
    cudaGetSymbolAddress((void**)&wthi, g_wthi);
    cudaGetSymbolAddress((void**)&wtlo, g_wtlo);

    cudaFuncSetAttribute(gemm_mma_bf16x3,
                         cudaFuncAttributeMaxDynamicSharedMemorySize, SMEM_DYN);

    const int ff_elems   = M_TOK * DM;
    const int attn_elems = M_TOK * 64;
    float* aw = (out_size >= ff_elems + attn_elems) ? (out + ff_elems) : nullptr;

    // ---- prep: split x; all-5 weight transpose+split; concat qkv bias -----
    split_kernel<<<(M_TOK * DM / 4 + 255) / 256, 256>>>(x, xhi, xlo, M_TOK * DM / 4);
    wconvert_kernel<<<dim3(32, 32, 5), dim3(32, 8)>>>(
        (const float*)d_in[1], (const float*)d_in[3], (const float*)d_in[5],
        (const float*)d_in[7], (const float*)d_in[9], wthi, wtlo);
    cudaMemcpyAsync(bqkv,        bq, 1024 * sizeof(float), cudaMemcpyDeviceToDevice);
    cudaMemcpyAsync(bqkv + 1024, bk, 1024 * sizeof(float), cudaMemcpyDeviceToDevice);
    cudaMemcpyAsync(bqkv + 2048, bv, 1024 * sizeof(float), cudaMemcpyDeviceToDevice);

    dim3 block(256);

    // ---- fused QKV projection: N=3072, packed [tok][3072] fp32 ------------
    gemm_mma_bf16x3<<<dim3(24, 128), block, SMEM_DYN>>>(xhi, xlo,
        wthi, wtlo, bqkv, qkv, nullptr, nullptr, 0, 3072);

    // ---- attention (emits bf16 split for FFN1) ----------------------------
    attn_kernel<<<M_TOK / 2, 256>>>(qkv, aohi, aolo, aw);

    // ---- FFN --------------------------------------------------------------
    gemm_mma_bf16x3<<<dim3(8, 128), block, SMEM_DYN>>>(aohi, aolo,
        wthi + 3 * (size_t)DM * DM, wtlo + 3 * (size_t)DM * DM, b1,
        nullptr, hhi, hlo, 1, 1024);
    gemm_mma_bf16x3<<<dim3(8, 128), block, SMEM_DYN>>>(hhi, hlo,
        wthi + 4 * (size_t)DM * DM, wtlo + 4 * (size_t)DM * DM, b2,
        out, nullptr, nullptr, 0, 1024);
}